// round 13
// baseline (speedup 1.0000x reference)
#include <cuda_runtime.h>
#include <cuda_fp16.h>
#include <stdint.h>

// ============================================================================
// GConvGRU (K=1 Cheb, H0=0) collapses to:
//   Z  = sigmoid(x@Wxz + bxz + bhz)
//   Ht = tanh   (x@Wxh + bxh + bhh)
//   h  = elu((1-Z)*Ht)
//   out = h@Wlin + blin
// sm_100 toolchain (no tcgen05). Fused fp16 mma.sync + ldmatrix, 512 threads
// / 16 warps (4m x 4n), MT=128. Gates use fp16 ACCUMULATORS (error damped by
// gate activations; ~1e-4 end-to-end) -> warp tile 32x64 for z+h in ONE pass.
// Readout keeps fp32 accumulators. Weights staged via cp.async k32 double
// buffer. Weights pre-transposed to N-major fp16 by prep kernel.
// ============================================================================

#define M_NODES 100000
#define CH      256
#define MT      128
#define NTILES  782
#define THREADS 512

#define XSTRIDE 528               // 33 x 16B units -> ldmatrix conflict-free
#define WSTRIDE 80                // 5 x 16B units  -> ldmatrix conflict-free
#define WMATG   20480             // 256 rows x 80B (one gate matrix, k32 chunk)
#define WBUFG   (2 * WMATG)       // z + h per stage

#define OFF_BZ  0
#define OFF_BH  1024
#define OFF_BL  2048
#define OFF_X   3072
#define OFF_H   (OFF_X + MT * XSTRIDE)     // 70656
#define OFF_W   (OFF_H + MT * XSTRIDE)     // 138240 ; 2 stages x WBUFG
#define SMEM_TOTAL (OFF_W + 2 * WBUFG)     // 220160 B

#define L2E 1.4426950408889634f

static __device__ __half g_wt[3 * CH * CH];    // n-major fp16: [w][n][k]

// ---------------------------------------------------------------------------
__device__ __forceinline__ uint32_t smem_u32(const void* p) {
    uint32_t a;
    asm("{ .reg .u64 t; cvta.to.shared.u64 t, %1; cvt.u32.u64 %0, t; }"
        : "=r"(a) : "l"(p));
    return a;
}
__device__ __forceinline__ float fex2(float x) {
    float y; asm("ex2.approx.f32 %0, %1;" : "=f"(y) : "f"(x)); return y;
}
__device__ __forceinline__ float frcp(float x) {
    float y; asm("rcp.approx.f32 %0, %1;" : "=f"(y) : "f"(x)); return y;
}
__device__ __forceinline__ void cpa16(uint32_t s, const void* g) {
    asm volatile("cp.async.ca.shared.global [%0], [%1], 16;"
                 :: "r"(s), "l"(g) : "memory");
}
#define CP_COMMIT() asm volatile("cp.async.commit_group;" ::: "memory")
#define CP_WAIT0()  asm volatile("cp.async.wait_group 0;" ::: "memory")

__device__ __forceinline__ void ldsm4(uint32_t r[4], uint32_t addr) {
    asm volatile("ldmatrix.sync.aligned.m8n8.x4.shared.b16 {%0,%1,%2,%3}, [%4];"
                 : "=r"(r[0]), "=r"(r[1]), "=r"(r[2]), "=r"(r[3]) : "r"(addr));
}
// fp32-accumulator mma (readout)
__device__ __forceinline__ void mma16f(float c[4], const uint32_t a[4],
                                       uint32_t b0, uint32_t b1) {
    asm volatile(
        "mma.sync.aligned.m16n8k16.row.col.f32.f16.f16.f32 "
        "{%0,%1,%2,%3}, {%4,%5,%6,%7}, {%8,%9}, {%0,%1,%2,%3};"
        : "+f"(c[0]), "+f"(c[1]), "+f"(c[2]), "+f"(c[3])
        : "r"(a[0]), "r"(a[1]), "r"(a[2]), "r"(a[3]), "r"(b0), "r"(b1));
}
// fp16-accumulator mma (gates)
__device__ __forceinline__ void mma16h(uint32_t c[2], const uint32_t a[4],
                                       uint32_t b0, uint32_t b1) {
    asm volatile(
        "mma.sync.aligned.m16n8k16.row.col.f16.f16.f16.f16 "
        "{%0,%1}, {%2,%3,%4,%5}, {%6,%7}, {%0,%1};"
        : "+r"(c[0]), "+r"(c[1])
        : "r"(a[0]), "r"(a[1]), "r"(a[2]), "r"(a[3]), "r"(b0), "r"(b1));
}
__device__ __forceinline__ uint32_t packh2(float a, float b) {
    __half2 h = __floats2half2_rn(a, b);
    return *reinterpret_cast<uint32_t*>(&h);
}

// ---------------------------------------------------------------------------
// Prep: Wt[n][k] = fp16(W[k][n]) for Wxz, Wxh, Wlin (n-major)
// ---------------------------------------------------------------------------
__global__ void prep_kernel(const float* __restrict__ Wz,
                            const float* __restrict__ Wh,
                            const float* __restrict__ Wl) {
    __shared__ float t[32][33];
    const float* W = (blockIdx.z == 0) ? Wz : (blockIdx.z == 1) ? Wh : Wl;
    __half* Wt = g_wt + (size_t)blockIdx.z * CH * CH;
    int n0 = blockIdx.x * 32, k0 = blockIdx.y * 32;
    int tx = threadIdx.x, ty = threadIdx.y;   // 32 x 8
#pragma unroll
    for (int r = 0; r < 4; r++)
        t[ty + r * 8][tx] = W[(size_t)(k0 + ty + r * 8) * CH + n0 + tx];
    __syncthreads();
#pragma unroll
    for (int r = 0; r < 4; r++)
        Wt[(size_t)(n0 + ty + r * 8) * CH + k0 + tx] =
            __float2half_rn(t[tx][ty + r * 8]);
}

// ---------------------------------------------------------------------------
// Fused main kernel: one CTA per 128-row tile, 16 warps (4m x 4n)
// ---------------------------------------------------------------------------
__global__ void __launch_bounds__(THREADS, 1) fused_kernel(
    const float* __restrict__ x,
    const float* __restrict__ bxz, const float* __restrict__ bhz,
    const float* __restrict__ bxh, const float* __restrict__ bhh,
    const float* __restrict__ blin,
    float* __restrict__ out)
{
    extern __shared__ char smem[];
    const uint32_t sbase = smem_u32(smem);
    const int tid = threadIdx.x, wid = tid >> 5, lane = tid & 31;
    const int grp = lane >> 2, t4 = lane & 3;
    const int wm = wid & 3, wn = wid >> 2;      // 4m x 4n
    const int wr = wm * 32;
    const int mbase = blockIdx.x * MT;

    float* bzs = (float*)(smem + OFF_BZ);
    float* bhs = (float*)(smem + OFF_BH);
    float* bls = (float*)(smem + OFF_BL);
    if (tid < CH) {
        bzs[tid] = bxz[tid] + bhz[tid];
        bhs[tid] = bxh[tid] + bhh[tid];
        bls[tid] = blin[tid];
    }

    const __half* wtz = g_wt;
    const __half* wtl = g_wt + 2 * CH * CH;

    // ---- cp.async weight staging ----
    // gates k32 chunk: z and h, 256 rows x 64B each -> 4 cpa16/thread
    const int srow = tid >> 1;                 // 0..255  (2 chunks16/thread/mat)
    const int sui  = (tid & 1) * 2;            // 16B-chunk 0/2 base
    auto cpW = [&](int ch, int buf) {
        const __half* gz = wtz + (size_t)srow * CH + ch * 32 + sui * 8;
        uint32_t s = sbase + OFF_W + buf * WBUFG + srow * WSTRIDE + sui * 16;
        cpa16(s, gz);            cpa16(s + 16, gz + 8);               // z
        cpa16(s + WMATG, gz + CH * CH);
        cpa16(s + WMATG + 16, gz + CH * CH + 8);                      // h
    };
    auto cpL = [&](int ch, int buf) {
        const __half* gl = wtl + (size_t)srow * CH + ch * 32 + sui * 8;
        uint32_t s = sbase + OFF_W + buf * WBUFG + srow * WSTRIDE + sui * 16;
        cpa16(s, gl);            cpa16(s + 16, gl + 8);
    };

    cpW(0, 0); CP_COMMIT();

    // ---- stage X tile (fp32 -> fp16, resident) ----
#pragma unroll
    for (int i = 0; i < 8; i++) {
        int idx = i * THREADS + tid;           // 0..4095
        int r = idx >> 5, c16 = idx & 31;
        int gr = mbase + r;
        float4 v0 = make_float4(0.f, 0.f, 0.f, 0.f), v1 = v0;
        if (gr < M_NODES) {
            const float* p = x + (size_t)gr * CH + c16 * 8;
            v0 = *(const float4*)(p);
            v1 = *(const float4*)(p + 4);
        }
        uint4 u = make_uint4(packh2(v0.x, v0.y), packh2(v0.z, v0.w),
                             packh2(v1.x, v1.y), packh2(v1.z, v1.w));
        *(uint4*)(smem + OFF_X + r * XSTRIDE + c16 * 16) = u;
    }

    // per-lane ldmatrix base addresses
    const uint32_t xa = sbase + OFF_X + (uint32_t)(wr + (lane & 15)) * XSTRIDE
                        + ((lane >> 4) << 4);
    const uint32_t ha = sbase + OFF_H + (uint32_t)(wr + (lane & 15)) * XSTRIDE
                        + ((lane >> 4) << 4);
    const uint32_t wb = sbase + OFF_W + (uint32_t)(wn * 64 + (lane & 15)) * WSTRIDE
                        + ((lane >> 4) << 4);

    // ======================= gates: single pass, fp16 accs ============
    {
        uint32_t az[2][8][2], ah[2][8][2];     // [mi][nt][reg], fp16x2
#pragma unroll
        for (int i = 0; i < 2; i++)
#pragma unroll
            for (int j = 0; j < 8; j++) {
                az[i][j][0] = 0u; az[i][j][1] = 0u;
                ah[i][j][0] = 0u; ah[i][j][1] = 0u;
            }

        CP_WAIT0();
        __syncthreads();          // X + W chunk 0 ready
#pragma unroll 1
        for (int ch = 0; ch < 8; ch++) {
            const int buf = ch & 1;
            if (ch < 7) { cpW(ch + 1, buf ^ 1); CP_COMMIT(); }
#pragma unroll
            for (int ks = 0; ks < 2; ks++) {
                uint32_t a0[4], a1[4];
                ldsm4(a0, xa + ch * 64 + ks * 32);
                ldsm4(a1, xa + 16 * XSTRIDE + ch * 64 + ks * 32);
                const uint32_t wbc = wb + buf * WBUFG + ks * 32;
#pragma unroll
                for (int p = 0; p < 4; p++) {
                    uint32_t b4[4];
                    ldsm4(b4, wbc + p * 16 * WSTRIDE);
                    mma16h(az[0][2 * p],     a0, b4[0], b4[2]);
                    mma16h(az[1][2 * p],     a1, b4[0], b4[2]);
                    mma16h(az[0][2 * p + 1], a0, b4[1], b4[3]);
                    mma16h(az[1][2 * p + 1], a1, b4[1], b4[3]);
                }
#pragma unroll
                for (int p = 0; p < 4; p++) {
                    uint32_t b4[4];
                    ldsm4(b4, wbc + WMATG + p * 16 * WSTRIDE);
                    mma16h(ah[0][2 * p],     a0, b4[0], b4[2]);
                    mma16h(ah[1][2 * p],     a1, b4[0], b4[2]);
                    mma16h(ah[0][2 * p + 1], a0, b4[1], b4[3]);
                    mma16h(ah[1][2 * p + 1], a1, b4[1], b4[3]);
                }
            }
            if (ch < 7) { CP_WAIT0(); __syncthreads(); }
        }

        // prefetch readout chunk 0 under the epilogue (gates buf0 reads were
        // fenced by ch==6's sync; ch==7 read buf1)
        cpL(0, 0); CP_COMMIT();

        // ---- GRU/elu epilogue -> H (fp16 smem) ----
#pragma unroll
        for (int mi = 0; mi < 2; mi++) {
#pragma unroll
            for (int nt = 0; nt < 8; nt++) {
                int col = wn * 64 + nt * 8 + 2 * t4;
                float bz0 = bzs[col], bz1 = bzs[col + 1];
                float bh0 = bhs[col], bh1 = bhs[col + 1];
#pragma unroll
                for (int hh = 0; hh < 2; hh++) {
                    int row = wr + mi * 16 + grp + hh * 8;
                    float2 fz = __half22float2(
                        *reinterpret_cast<__half2*>(&az[mi][nt][hh]));
                    float2 fh = __half22float2(
                        *reinterpret_cast<__half2*>(&ah[mi][nt][hh]));
                    float a0 = fz.x + bz0, a1 = fz.y + bz1;
                    float c0 = fh.x + bh0, c1 = fh.y + bh1;
                    float zp0 = frcp(1.f + fex2(a0 * L2E));      // 1 - sigmoid
                    float zp1 = frcp(1.f + fex2(a1 * L2E));
                    float t0 = 1.f - 2.f * frcp(fex2(c0 * (2.f * L2E)) + 1.f);
                    float t1 = 1.f - 2.f * frcp(fex2(c1 * (2.f * L2E)) + 1.f);
                    float v0 = zp0 * t0, v1 = zp1 * t1;
                    v0 = (v0 > 0.f) ? v0 : (fex2(v0 * L2E) - 1.f);
                    v1 = (v1 > 0.f) ? v1 : (fex2(v1 * L2E) - 1.f);
                    *(uint32_t*)(smem + OFF_H + row * XSTRIDE + col * 2) =
                        packh2(v0, v1);
                }
            }
        }
    }
    CP_WAIT0();
    __syncthreads();              // H complete + Wl chunk 0 ready

    // ======================= readout: out = H @ WlT + bl ===============
    {
        float o[2][8][4];
#pragma unroll
        for (int i = 0; i < 2; i++)
#pragma unroll
            for (int j = 0; j < 8; j++)
#pragma unroll
                for (int k = 0; k < 4; k++) o[i][j][k] = 0.f;

#pragma unroll 1
        for (int ch = 0; ch < 8; ch++) {
            const int buf = ch & 1;
            if (ch < 7) { cpL(ch + 1, buf ^ 1); CP_COMMIT(); }
#pragma unroll
            for (int ks = 0; ks < 2; ks++) {
                uint32_t a0[4], a1[4];
                ldsm4(a0, ha + ch * 64 + ks * 32);
                ldsm4(a1, ha + 16 * XSTRIDE + ch * 64 + ks * 32);
                const uint32_t wbc = wb + buf * WBUFG + ks * 32;
#pragma unroll
                for (int p = 0; p < 4; p++) {
                    uint32_t b4[4];
                    ldsm4(b4, wbc + p * 16 * WSTRIDE);
                    mma16f(o[0][2 * p],     a0, b4[0], b4[2]);
                    mma16f(o[1][2 * p],     a1, b4[0], b4[2]);
                    mma16f(o[0][2 * p + 1], a0, b4[1], b4[3]);
                    mma16f(o[1][2 * p + 1], a1, b4[1], b4[3]);
                }
            }
            if (ch < 7) { CP_WAIT0(); __syncthreads(); }
        }

        // ---- biased store ----
#pragma unroll
        for (int mi = 0; mi < 2; mi++) {
#pragma unroll
            for (int nt = 0; nt < 8; nt++) {
                int col = wn * 64 + nt * 8 + 2 * t4;
                float b0 = bls[col], b1 = bls[col + 1];
#pragma unroll
                for (int hh = 0; hh < 2; hh++) {
                    int gr = mbase + wr + mi * 16 + grp + hh * 8;
                    if (gr < M_NODES) {
                        *(float2*)(out + (size_t)gr * CH + col) =
                            make_float2(o[mi][nt][2 * hh + 0] + b0,
                                        o[mi][nt][2 * hh + 1] + b1);
                    }
                }
            }
        }
    }
}

// ---------------------------------------------------------------------------
extern "C" void kernel_launch(void* const* d_in, const int* in_sizes, int n_in,
                              void* d_out, int out_size)
{
    const float* x     = (const float*)d_in[0];
    const float* W_xz  = (const float*)d_in[3];
    const float* b_xz  = (const float*)d_in[4];
    const float* b_hz  = (const float*)d_in[6];
    const float* W_xh  = (const float*)d_in[11];
    const float* b_xh  = (const float*)d_in[12];
    const float* b_hh  = (const float*)d_in[14];
    const float* W_lin = (const float*)d_in[15];
    const float* b_lin = (const float*)d_in[16];
    float* out = (float*)d_out;

    static bool attr_done = false;
    if (!attr_done) {
        (void)cudaFuncSetAttribute(fused_kernel,
                                   cudaFuncAttributeMaxDynamicSharedMemorySize,
                                   SMEM_TOTAL);
        attr_done = true;
    }

    prep_kernel<<<dim3(8, 8, 3), dim3(32, 8)>>>(W_xz, W_xh, W_lin);
    fused_kernel<<<NTILES, THREADS, SMEM_TOTAL>>>(x, b_xz, b_hz, b_xh, b_hh,
                                                  b_lin, out);
}